// round 1
// baseline (speedup 1.0000x reference)
#include <cuda_runtime.h>
#include <math.h>

// Problem constants
#define Bb 128
#define Ss 128
#define Nn 24
#define Ff 16
#define Hh 32
#define IS 384      // N*F
#define HS 768      // N*H
#define GS 3072     // 4*HS
#define MROWS 16384 // B*S

#define HIDDEN_ELEMS (Bb*Ss*HS)   // 12582912
#define STATE_ELEMS  (Bb*HS)      // 98304

// Device scratch (no cudaMalloc allowed)
__device__ float g_Wm[IS * GS];          // 4.7 MB
__device__ float g_Um[HS * GS];          // 9.4 MB
__device__ float g_xg[MROWS * GS];       // 201 MB
__device__ float g_gp[3][Bb * GS];       // 4.5 MB  (split-K partials)
__device__ float g_h0buf[STATE_ELEMS];
__device__ float g_h1buf[STATE_ELEMS];
__device__ float g_c[STATE_ELEMS];

// ---------- f32x2 packed-FMA helpers (Blackwell FFMA2 via PTX) ----------
__device__ __forceinline__ void ffma2(unsigned long long& acc,
                                      unsigned long long a,
                                      unsigned long long b) {
    asm("fma.rn.f32x2 %0, %1, %2, %0;" : "+l"(acc) : "l"(a), "l"(b));
}
__device__ __forceinline__ unsigned long long pack2(float a) {
    unsigned long long r;
    asm("mov.b64 %0, {%1, %1};" : "=l"(r) : "f"(a));
    return r;
}
__device__ __forceinline__ void unpack2(unsigned long long v, float& lo, float& hi) {
    asm("mov.b64 {%0, %1}, %2;" : "=f"(lo), "=f"(hi) : "l"(v));
}

// ---------- weight masking: Wm = W .* GW, Um = U .* GU ----------
__global__ void mask_kernel(const float* __restrict__ W,
                            const float* __restrict__ U,
                            const float* __restrict__ G) {
    int idx = blockIdx.x * blockDim.x + threadIdx.x;
    if (idx < IS * GS) {
        int i = idx / GS;
        int j = idx % GS;
        int n1 = i >> 4;          // / F
        int n2 = (j % HS) >> 5;   // / H
        g_Wm[idx] = W[idx] * G[n1 * Nn + n2];
    }
    if (idx < HS * GS) {
        int i = idx / GS;
        int j = idx % GS;
        int n1 = i >> 5;          // / H
        int n2 = (j % HS) >> 5;
        g_Um[idx] = U[idx] * G[n1 * Nn + n2];
    }
}

__global__ void init_kernel(const float* __restrict__ h0,
                            const float* __restrict__ c0) {
    int idx = blockIdx.x * blockDim.x + threadIdx.x;
    if (idx < STATE_ELEMS) {
        g_h0buf[idx] = h0[idx];
        g_c[idx] = c0[idx];
    }
}

// ---------- GEMM 1: g_xg[16384,3072] = X[16384,384] @ g_Wm + bias ----------
// 64x64 tile, BK=16, 256 threads, 4x4 per thread, f32x2 accumulators.
#define BM 64
#define BN 64
#define BK 16

__global__ __launch_bounds__(256) void gemm_xw(const float* __restrict__ X,
                                               const float* __restrict__ bias) {
    __shared__ float As[BK][BM + 4];
    __shared__ float Bs[BK][BN];
    const int tx = threadIdx.x & 15;
    const int ty = threadIdx.x >> 4;
    const int bm = blockIdx.y * BM;
    const int bn = blockIdx.x * BN;

    unsigned long long acc[4][2];
#pragma unroll
    for (int i = 0; i < 4; i++) { acc[i][0] = 0ULL; acc[i][1] = 0ULL; }

    const int lm = threadIdx.x >> 2;          // A-load row
    const int lk = (threadIdx.x & 3) * 4;     // A-load k offset
    const int lr = threadIdx.x >> 4;          // B-load row
    const int lc = (threadIdx.x & 15) * 4;    // B-load col

    for (int k0 = 0; k0 < IS; k0 += BK) {
        float4 av = *reinterpret_cast<const float4*>(&X[(bm + lm) * IS + k0 + lk]);
        As[lk + 0][lm] = av.x; As[lk + 1][lm] = av.y;
        As[lk + 2][lm] = av.z; As[lk + 3][lm] = av.w;
        *reinterpret_cast<float4*>(&Bs[lr][lc]) =
            *reinterpret_cast<const float4*>(&g_Wm[(k0 + lr) * GS + bn + lc]);
        __syncthreads();
#pragma unroll
        for (int kk = 0; kk < BK; kk++) {
            float4 a4 = *reinterpret_cast<const float4*>(&As[kk][ty * 4]);
            ulonglong2 b2 = *reinterpret_cast<const ulonglong2*>(&Bs[kk][tx * 4]);
            unsigned long long a0 = pack2(a4.x), a1 = pack2(a4.y),
                               a2 = pack2(a4.z), a3 = pack2(a4.w);
            ffma2(acc[0][0], a0, b2.x); ffma2(acc[0][1], a0, b2.y);
            ffma2(acc[1][0], a1, b2.x); ffma2(acc[1][1], a1, b2.y);
            ffma2(acc[2][0], a2, b2.x); ffma2(acc[2][1], a2, b2.y);
            ffma2(acc[3][0], a3, b2.x); ffma2(acc[3][1], a3, b2.y);
        }
        __syncthreads();
    }

    float4 bv = *reinterpret_cast<const float4*>(&bias[bn + tx * 4]);
#pragma unroll
    for (int i = 0; i < 4; i++) {
        float l0, h0v, l1, h1v;
        unpack2(acc[i][0], l0, h0v);
        unpack2(acc[i][1], l1, h1v);
        float4 o = make_float4(l0 + bv.x, h0v + bv.y, l1 + bv.z, h1v + bv.w);
        *reinterpret_cast<float4*>(&g_xg[(bm + ty * 4 + i) * GS + bn + tx * 4]) = o;
    }
}

// ---------- GEMM 2 (per step): g_gp[z] = h @ Um[kslice] (split-K, beta=0) ----------
__global__ __launch_bounds__(256) void gemm_hu(int s) {
    const float* __restrict__ Hmat = (s & 1) ? g_h1buf : g_h0buf;
    __shared__ float As[BK][BM + 4];
    __shared__ float Bs[BK][BN];
    const int tx = threadIdx.x & 15;
    const int ty = threadIdx.x >> 4;
    const int bm = blockIdx.y * BM;
    const int bn = blockIdx.x * BN;
    const int kbase = blockIdx.z * 256;   // HS/3 = 256 per slice

    unsigned long long acc[4][2];
#pragma unroll
    for (int i = 0; i < 4; i++) { acc[i][0] = 0ULL; acc[i][1] = 0ULL; }

    const int lm = threadIdx.x >> 2;
    const int lk = (threadIdx.x & 3) * 4;
    const int lr = threadIdx.x >> 4;
    const int lc = (threadIdx.x & 15) * 4;

    for (int k0 = 0; k0 < 256; k0 += BK) {
        float4 av = *reinterpret_cast<const float4*>(&Hmat[(bm + lm) * HS + kbase + k0 + lk]);
        As[lk + 0][lm] = av.x; As[lk + 1][lm] = av.y;
        As[lk + 2][lm] = av.z; As[lk + 3][lm] = av.w;
        *reinterpret_cast<float4*>(&Bs[lr][lc]) =
            *reinterpret_cast<const float4*>(&g_Um[(kbase + k0 + lr) * GS + bn + lc]);
        __syncthreads();
#pragma unroll
        for (int kk = 0; kk < BK; kk++) {
            float4 a4 = *reinterpret_cast<const float4*>(&As[kk][ty * 4]);
            ulonglong2 b2 = *reinterpret_cast<const ulonglong2*>(&Bs[kk][tx * 4]);
            unsigned long long a0 = pack2(a4.x), a1 = pack2(a4.y),
                               a2 = pack2(a4.z), a3 = pack2(a4.w);
            ffma2(acc[0][0], a0, b2.x); ffma2(acc[0][1], a0, b2.y);
            ffma2(acc[1][0], a1, b2.x); ffma2(acc[1][1], a1, b2.y);
            ffma2(acc[2][0], a2, b2.x); ffma2(acc[2][1], a2, b2.y);
            ffma2(acc[3][0], a3, b2.x); ffma2(acc[3][1], a3, b2.y);
        }
        __syncthreads();
    }

    float* __restrict__ out = g_gp[blockIdx.z];
#pragma unroll
    for (int i = 0; i < 4; i++) {
        float l0, h0v, l1, h1v;
        unpack2(acc[i][0], l0, h0v);
        unpack2(acc[i][1], l1, h1v);
        float4 o = make_float4(l0, h0v, l1, h1v);
        *reinterpret_cast<float4*>(&out[(bm + ty * 4 + i) * GS + bn + tx * 4]) = o;
    }
}

// ---------- per-step pointwise LSTM update + output writes ----------
__global__ __launch_bounds__(256) void lstm_update(float* __restrict__ out, int s) {
    int idx = blockIdx.x * blockDim.x + threadIdx.x;
    if (idx >= STATE_ELEMS) return;
    int b = idx / HS;
    int j = idx % HS;
    const int row = b * GS;
    const int xrow = (b * Ss + s) * GS;

    float v[4];
#pragma unroll
    for (int g = 0; g < 4; g++) {
        int col = g * HS + j;
        v[g] = g_xg[xrow + col] + g_gp[0][row + col] + g_gp[1][row + col] + g_gp[2][row + col];
    }
    float ig = 1.0f / (1.0f + expf(-v[0]));
    float fg = 1.0f / (1.0f + expf(-v[1]));
    float gg = tanhf(v[2]);
    float og = 1.0f / (1.0f + expf(-v[3]));

    float c = fg * g_c[idx] + ig * gg;
    g_c[idx] = c;
    float h = og * tanhf(c);

    float* hnext = (s & 1) ? g_h0buf : g_h1buf;
    hnext[idx] = h;

    // hidden_seq[b, s, j]
    out[(b * Ss + s) * HS + j] = h;
    if (s == Ss - 1) {
        out[HIDDEN_ELEMS + idx] = h;                 // final h
        out[HIDDEN_ELEMS + STATE_ELEMS + idx] = c;   // final c
    }
}

extern "C" void kernel_launch(void* const* d_in, const int* in_sizes, int n_in,
                              void* d_out, int out_size) {
    const float* x    = (const float*)d_in[0];
    const float* h0   = (const float*)d_in[1];
    const float* c0   = (const float*)d_in[2];
    const float* W    = (const float*)d_in[3];
    const float* U    = (const float*)d_in[4];
    const float* bias = (const float*)d_in[5];
    const float* G    = (const float*)d_in[6];
    float* out = (float*)d_out;

    (void)in_sizes; (void)n_in; (void)out_size;

    // 1) mask weights (covers both Wm and Um ranges)
    mask_kernel<<<(HS * GS + 255) / 256, 256>>>(W, U, G);
    // 2) init state
    init_kernel<<<(STATE_ELEMS + 255) / 256, 256>>>(h0, c0);
    // 3) big input-projection GEMM: xg = X @ Wm + bias
    gemm_xw<<<dim3(GS / BN, MROWS / BM), 256>>>(x, bias);
    // 4) sequential scan
    for (int s = 0; s < Ss; s++) {
        gemm_hu<<<dim3(GS / BN, Bb / BM, 3), 256>>>(s);
        lstm_update<<<(STATE_ELEMS + 255) / 256, 256>>>(out, s);
    }
}

// round 2
// speedup vs baseline: 1.0053x; 1.0053x over previous
#include <cuda_runtime.h>
#include <math.h>

// Problem constants
#define Bb 128
#define Ss 128
#define Nn 24
#define Ff 16
#define Hh 32
#define IS 384      // N*F
#define HS 768      // N*H
#define GS 3072     // 4*HS
#define MROWS 16384 // B*S

#define HIDDEN_ELEMS (Bb*Ss*HS)   // 12582912
#define STATE_ELEMS  (Bb*HS)      // 98304

// Device scratch (no cudaMalloc allowed)
__device__ float g_Wm[IS * GS];          // 4.7 MB
__device__ float g_Um[HS * GS];          // 9.4 MB
__device__ float g_xg[MROWS * GS];       // 201 MB
__device__ float g_gp[3][Bb * GS];       // 4.5 MB  (split-K partials)
__device__ float g_h0buf[STATE_ELEMS];
__device__ float g_h1buf[STATE_ELEMS];
__device__ float g_c[STATE_ELEMS];

// ---------- f32x2 packed-FMA helpers (Blackwell FFMA2 via PTX) ----------
__device__ __forceinline__ void ffma2(unsigned long long& acc,
                                      unsigned long long a,
                                      unsigned long long b) {
    asm("fma.rn.f32x2 %0, %1, %2, %0;" : "+l"(acc) : "l"(a), "l"(b));
}
__device__ __forceinline__ unsigned long long pack2(float a) {
    unsigned long long r;
    asm("mov.b64 %0, {%1, %1};" : "=l"(r) : "f"(a));
    return r;
}
__device__ __forceinline__ void unpack2(unsigned long long v, float& lo, float& hi) {
    asm("mov.b64 {%0, %1}, %2;" : "=f"(lo), "=f"(hi) : "l"(v));
}

// ---------- weight masking: Wm = W .* GW, Um = U .* GU ----------
__global__ void mask_kernel(const float* __restrict__ W,
                            const float* __restrict__ U,
                            const float* __restrict__ G) {
    int idx = blockIdx.x * blockDim.x + threadIdx.x;
    if (idx < IS * GS) {
        int i = idx / GS;
        int j = idx % GS;
        int n1 = i >> 4;          // / F
        int n2 = (j % HS) >> 5;   // / H
        g_Wm[idx] = W[idx] * G[n1 * Nn + n2];
    }
    if (idx < HS * GS) {
        int i = idx / GS;
        int j = idx % GS;
        int n1 = i >> 5;          // / H
        int n2 = (j % HS) >> 5;
        g_Um[idx] = U[idx] * G[n1 * Nn + n2];
    }
}

__global__ void init_kernel(const float* __restrict__ h0,
                            const float* __restrict__ c0) {
    int idx = blockIdx.x * blockDim.x + threadIdx.x;
    if (idx < STATE_ELEMS) {
        g_h0buf[idx] = h0[idx];
        g_c[idx] = c0[idx];
    }
}

// ---------- GEMM 1: g_xg[16384,3072] = X[16384,384] @ g_Wm + bias ----------
// 64x64 tile, BK=16, 256 threads, 4x4 per thread, f32x2 accumulators.
#define BM 64
#define BN 64
#define BK 16

__global__ __launch_bounds__(256) void gemm_xw(const float* __restrict__ X,
                                               const float* __restrict__ bias) {
    __shared__ float As[BK][BM + 4];
    __shared__ float Bs[BK][BN];
    const int tx = threadIdx.x & 15;
    const int ty = threadIdx.x >> 4;
    const int bm = blockIdx.y * BM;
    const int bn = blockIdx.x * BN;

    unsigned long long acc[4][2];
#pragma unroll
    for (int i = 0; i < 4; i++) { acc[i][0] = 0ULL; acc[i][1] = 0ULL; }

    const int lm = threadIdx.x >> 2;          // A-load row
    const int lk = (threadIdx.x & 3) * 4;     // A-load k offset
    const int lr = threadIdx.x >> 4;          // B-load row
    const int lc = (threadIdx.x & 15) * 4;    // B-load col

    for (int k0 = 0; k0 < IS; k0 += BK) {
        float4 av = *reinterpret_cast<const float4*>(&X[(bm + lm) * IS + k0 + lk]);
        As[lk + 0][lm] = av.x; As[lk + 1][lm] = av.y;
        As[lk + 2][lm] = av.z; As[lk + 3][lm] = av.w;
        *reinterpret_cast<float4*>(&Bs[lr][lc]) =
            *reinterpret_cast<const float4*>(&g_Wm[(k0 + lr) * GS + bn + lc]);
        __syncthreads();
#pragma unroll
        for (int kk = 0; kk < BK; kk++) {
            float4 a4 = *reinterpret_cast<const float4*>(&As[kk][ty * 4]);
            ulonglong2 b2 = *reinterpret_cast<const ulonglong2*>(&Bs[kk][tx * 4]);
            unsigned long long a0 = pack2(a4.x), a1 = pack2(a4.y),
                               a2 = pack2(a4.z), a3 = pack2(a4.w);
            ffma2(acc[0][0], a0, b2.x); ffma2(acc[0][1], a0, b2.y);
            ffma2(acc[1][0], a1, b2.x); ffma2(acc[1][1], a1, b2.y);
            ffma2(acc[2][0], a2, b2.x); ffma2(acc[2][1], a2, b2.y);
            ffma2(acc[3][0], a3, b2.x); ffma2(acc[3][1], a3, b2.y);
        }
        __syncthreads();
    }

    float4 bv = *reinterpret_cast<const float4*>(&bias[bn + tx * 4]);
#pragma unroll
    for (int i = 0; i < 4; i++) {
        float l0, h0v, l1, h1v;
        unpack2(acc[i][0], l0, h0v);
        unpack2(acc[i][1], l1, h1v);
        float4 o = make_float4(l0 + bv.x, h0v + bv.y, l1 + bv.z, h1v + bv.w);
        *reinterpret_cast<float4*>(&g_xg[(bm + ty * 4 + i) * GS + bn + tx * 4]) = o;
    }
}

// ---------- GEMM 2 (per step): g_gp[z] = h @ Um[kslice] (split-K, beta=0) ----------
__global__ __launch_bounds__(256) void gemm_hu(int s) {
    const float* __restrict__ Hmat = (s & 1) ? g_h1buf : g_h0buf;
    __shared__ float As[BK][BM + 4];
    __shared__ float Bs[BK][BN];
    const int tx = threadIdx.x & 15;
    const int ty = threadIdx.x >> 4;
    const int bm = blockIdx.y * BM;
    const int bn = blockIdx.x * BN;
    const int kbase = blockIdx.z * 256;   // HS/3 = 256 per slice

    unsigned long long acc[4][2];
#pragma unroll
    for (int i = 0; i < 4; i++) { acc[i][0] = 0ULL; acc[i][1] = 0ULL; }

    const int lm = threadIdx.x >> 2;
    const int lk = (threadIdx.x & 3) * 4;
    const int lr = threadIdx.x >> 4;
    const int lc = (threadIdx.x & 15) * 4;

    for (int k0 = 0; k0 < 256; k0 += BK) {
        float4 av = *reinterpret_cast<const float4*>(&Hmat[(bm + lm) * HS + kbase + k0 + lk]);
        As[lk + 0][lm] = av.x; As[lk + 1][lm] = av.y;
        As[lk + 2][lm] = av.z; As[lk + 3][lm] = av.w;
        *reinterpret_cast<float4*>(&Bs[lr][lc]) =
            *reinterpret_cast<const float4*>(&g_Um[(kbase + k0 + lr) * GS + bn + lc]);
        __syncthreads();
#pragma unroll
        for (int kk = 0; kk < BK; kk++) {
            float4 a4 = *reinterpret_cast<const float4*>(&As[kk][ty * 4]);
            ulonglong2 b2 = *reinterpret_cast<const ulonglong2*>(&Bs[kk][tx * 4]);
            unsigned long long a0 = pack2(a4.x), a1 = pack2(a4.y),
                               a2 = pack2(a4.z), a3 = pack2(a4.w);
            ffma2(acc[0][0], a0, b2.x); ffma2(acc[0][1], a0, b2.y);
            ffma2(acc[1][0], a1, b2.x); ffma2(acc[1][1], a1, b2.y);
            ffma2(acc[2][0], a2, b2.x); ffma2(acc[2][1], a2, b2.y);
            ffma2(acc[3][0], a3, b2.x); ffma2(acc[3][1], a3, b2.y);
        }
        __syncthreads();
    }

    float* __restrict__ out = g_gp[blockIdx.z];
#pragma unroll
    for (int i = 0; i < 4; i++) {
        float l0, h0v, l1, h1v;
        unpack2(acc[i][0], l0, h0v);
        unpack2(acc[i][1], l1, h1v);
        float4 o = make_float4(l0, h0v, l1, h1v);
        *reinterpret_cast<float4*>(&out[(bm + ty * 4 + i) * GS + bn + tx * 4]) = o;
    }
}

// ---------- per-step pointwise LSTM update + output writes ----------
__global__ __launch_bounds__(256) void lstm_update(float* __restrict__ out, int s) {
    int idx = blockIdx.x * blockDim.x + threadIdx.x;
    if (idx >= STATE_ELEMS) return;
    int b = idx / HS;
    int j = idx % HS;
    const int row = b * GS;
    const int xrow = (b * Ss + s) * GS;

    float v[4];
#pragma unroll
    for (int g = 0; g < 4; g++) {
        int col = g * HS + j;
        v[g] = g_xg[xrow + col] + g_gp[0][row + col] + g_gp[1][row + col] + g_gp[2][row + col];
    }
    float ig = 1.0f / (1.0f + expf(-v[0]));
    float fg = 1.0f / (1.0f + expf(-v[1]));
    float gg = tanhf(v[2]);
    float og = 1.0f / (1.0f + expf(-v[3]));

    float c = fg * g_c[idx] + ig * gg;
    g_c[idx] = c;
    float h = og * tanhf(c);

    float* hnext = (s & 1) ? g_h0buf : g_h1buf;
    hnext[idx] = h;

    // hidden_seq[b, s, j]
    out[(b * Ss + s) * HS + j] = h;
    if (s == Ss - 1) {
        out[HIDDEN_ELEMS + idx] = h;                 // final h
        out[HIDDEN_ELEMS + STATE_ELEMS + idx] = c;   // final c
    }
}

extern "C" void kernel_launch(void* const* d_in, const int* in_sizes, int n_in,
                              void* d_out, int out_size) {
    const float* x    = (const float*)d_in[0];
    const float* h0   = (const float*)d_in[1];
    const float* c0   = (const float*)d_in[2];
    const float* W    = (const float*)d_in[3];
    const float* U    = (const float*)d_in[4];
    const float* bias = (const float*)d_in[5];
    const float* G    = (const float*)d_in[6];
    float* out = (float*)d_out;

    (void)in_sizes; (void)n_in; (void)out_size;

    // 1) mask weights (covers both Wm and Um ranges)
    mask_kernel<<<(HS * GS + 255) / 256, 256>>>(W, U, G);
    // 2) init state
    init_kernel<<<(STATE_ELEMS + 255) / 256, 256>>>(h0, c0);
    // 3) big input-projection GEMM: xg = X @ Wm + bias
    gemm_xw<<<dim3(GS / BN, MROWS / BM), 256>>>(x, bias);
    // 4) sequential scan
    for (int s = 0; s < Ss; s++) {
        gemm_hu<<<dim3(GS / BN, Bb / BM, 3), 256>>>(s);
        lstm_update<<<(STATE_ELEMS + 255) / 256, 256>>>(out, s);
    }
}

// round 4
// speedup vs baseline: 1.1241x; 1.1182x over previous
#include <cuda_runtime.h>
#include <cuda_bf16.h>
#include <cstdint>

#define Bb 128
#define Ss 128
#define ISZ 384
#define HSZ 768
#define GSZ 3072
#define HID (Bb*Ss*HSZ)
#define STATE (Bb*HSZ)

// ---------------- device scratch ----------------
__device__ __nv_bfloat16 g_Umt_hi[GSZ*HSZ];   // Um^T permuted [n][k]
__device__ __nv_bfloat16 g_Umt_lo[GSZ*HSZ];
__device__ __nv_bfloat16 g_Wmt_hi[GSZ*ISZ];   // Wm^T permuted [n][k]
__device__ __nv_bfloat16 g_Wmt_lo[GSZ*ISZ];
__device__ __nv_bfloat16 g_Xh[Bb*Ss*ISZ];     // x reordered [(s*128+b)][k]
__device__ __nv_bfloat16 g_Xl[Bb*Ss*ISZ];
__device__ float g_xg[(size_t)Ss*Bb*GSZ];     // [s][b][n]
__device__ float g_part[6*Bb*GSZ];            // [ks][b][n]
__device__ float g_ht[STATE];                 // h fp32 [b][k]
__device__ float g_ct[STATE];                 // c fp32 [b][j]
__device__ float g_biasp[GSZ];                // permuted bias

// ---------------- helpers ----------------
__device__ __forceinline__ uint32_t smem_u32(const void* p) {
    uint32_t a;
    asm("{ .reg .u64 t; cvta.to.shared.u64 t, %1; cvt.u32.u64 %0, t; }" : "=r"(a) : "l"(p));
    return a;
}
__device__ __forceinline__ void ldsm4(uint32_t& r0, uint32_t& r1, uint32_t& r2, uint32_t& r3, uint32_t addr) {
    asm volatile("ldmatrix.sync.aligned.m8n8.x4.shared.b16 {%0,%1,%2,%3}, [%4];"
                 : "=r"(r0), "=r"(r1), "=r"(r2), "=r"(r3) : "r"(addr));
}
__device__ __forceinline__ void mma16816(float* c, uint32_t a0, uint32_t a1, uint32_t a2, uint32_t a3,
                                         uint32_t b0, uint32_t b1) {
    asm volatile("mma.sync.aligned.m16n8k16.row.col.f32.bf16.bf16.f32 "
                 "{%0,%1,%2,%3}, {%4,%5,%6,%7}, {%8,%9}, {%0,%1,%2,%3};"
                 : "+f"(c[0]), "+f"(c[1]), "+f"(c[2]), "+f"(c[3])
                 : "r"(a0), "r"(a1), "r"(a2), "r"(a3), "r"(b0), "r"(b1));
}
__device__ __forceinline__ unsigned short bf_hi(float x, float& rem) {
    __nv_bfloat16 h = __float2bfloat16(x);
    rem = x - __bfloat162float(h);
    return __bfloat16_as_ushort(h);
}
__device__ __forceinline__ float fsig(float x)  { return 1.0f / (1.0f + __expf(-x)); }
__device__ __forceinline__ float ftanh(float x) { return 2.0f / (1.0f + __expf(-2.0f * x)) - 1.0f; }

// SMEM tile geometry: 128 rows x 128 bf16, row stride 136 bf16 (272B) -> conflict-free ldmatrix
#define ROWB 272
#define TILEB (128 * ROWB)           // 34816
#define OFF_A_HI 0u
#define OFF_A_LO 34816u
#define OFF_B_HI 69632u
#define OFF_B_LO 104448u
#define SMEMSZ   139264

// bf16x3 MMA over one 128x128x128 tile pair (A hi/lo at sA, B hi/lo at sB)
__device__ __forceinline__ void mma_tile(uint32_t sA, uint32_t sB, int lane, int mb, int nb, float c[2][8][4]) {
    uint32_t aBase = sA + (uint32_t)(mb + (lane & 15)) * ROWB + (uint32_t)(lane >> 4) * 16;
    uint32_t bBase = sB + (uint32_t)(nb + ((lane >> 4) << 3) + (lane & 7)) * ROWB + (uint32_t)((lane >> 3) & 1) * 16;
#pragma unroll
    for (int p = 0; p < 3; p++) {
        uint32_t aOff = (p == 1) ? (uint32_t)TILEB : 0u;
        uint32_t bOff = (p == 2) ? (uint32_t)TILEB : 0u;
#pragma unroll
        for (int k0 = 0; k0 < 128; k0 += 16) {
            uint32_t a[2][4];
#pragma unroll
            for (int mi = 0; mi < 2; mi++)
                ldsm4(a[mi][0], a[mi][1], a[mi][2], a[mi][3],
                      aBase + aOff + (uint32_t)(mi * 16 * ROWB + k0 * 2));
#pragma unroll
            for (int nj = 0; nj < 4; nj++) {
                uint32_t b0, b1, b2, b3;
                ldsm4(b0, b1, b2, b3, bBase + bOff + (uint32_t)(nj * 16 * ROWB + k0 * 2));
#pragma unroll
                for (int mi = 0; mi < 2; mi++) {
                    mma16816(c[mi][nj * 2],     a[mi][0], a[mi][1], a[mi][2], a[mi][3], b0, b1);
                    mma16816(c[mi][nj * 2 + 1], a[mi][0], a[mi][1], a[mi][2], a[mi][3], b2, b3);
                }
            }
        }
    }
}

// stage C frags to smem then coalesced copy to gdst (+ b*3072 + n within 128-wide tile)
__device__ __forceinline__ void epilogue(char* smem, int lane, int wid, float c[2][8][4], float* gdst) {
    float* CS = reinterpret_cast<float*>(smem);   // stride 132 floats
    const int mb = (wid & 3) * 32, nb = (wid >> 2) * 64;
    const int r0 = mb + (lane >> 2);
    const int col0 = nb + (lane & 3) * 2;
#pragma unroll
    for (int mi = 0; mi < 2; mi++)
#pragma unroll
        for (int ni = 0; ni < 8; ni++) {
            float* p0 = &CS[(r0 + mi * 16) * 132 + col0 + ni * 8];
            p0[0] = c[mi][ni][0]; p0[1] = c[mi][ni][1];
            float* p1 = &CS[(r0 + mi * 16 + 8) * 132 + col0 + ni * 8];
            p1[0] = c[mi][ni][2]; p1[1] = c[mi][ni][3];
        }
    __syncthreads();
    const int t = threadIdx.x;
    const int b = t >> 1, half = t & 1;
    const float4* src = reinterpret_cast<const float4*>(&CS[b * 132 + half * 64]);
    float4* dst = reinterpret_cast<float4*>(gdst + (size_t)b * GSZ + half * 64);
#pragma unroll
    for (int q = 0; q < 16; q++) dst[q] = src[q];
}

// ---------------- one-time conversion kernels ----------------
__global__ void convU(const float* __restrict__ U, const float* __restrict__ G) {
    int idx = blockIdx.x * blockDim.x + threadIdx.x;
    if (idx >= GSZ * HSZ) return;
    int n = idx / HSZ, k = idx % HSZ;
    int j = n >> 2, g = n & 3;
    float v = U[(size_t)k * GSZ + g * HSZ + j] * G[(k >> 5) * 24 + (j >> 5)];
    float rem;
    g_Umt_hi[idx] = __ushort_as_bfloat16(bf_hi(v, rem));
    g_Umt_lo[idx] = __float2bfloat16(rem);
}
__global__ void convW(const float* __restrict__ W, const float* __restrict__ G) {
    int idx = blockIdx.x * blockDim.x + threadIdx.x;
    if (idx >= GSZ * ISZ) return;
    int n = idx / ISZ, k = idx % ISZ;
    int j = n >> 2, g = n & 3;
    float v = W[(size_t)k * GSZ + g * HSZ + j] * G[(k >> 4) * 24 + (j >> 5)];
    float rem;
    g_Wmt_hi[idx] = __ushort_as_bfloat16(bf_hi(v, rem));
    g_Wmt_lo[idx] = __float2bfloat16(rem);
}
__global__ void convX(const float* __restrict__ x) {
    int idx = blockIdx.x * blockDim.x + threadIdx.x;
    if (idx >= Bb * Ss * ISZ) return;
    int f = idx % ISZ, r = idx / ISZ;
    int s = r >> 7, b = r & 127;
    float v = x[((size_t)b * Ss + s) * ISZ + f];
    float rem;
    g_Xh[idx] = __ushort_as_bfloat16(bf_hi(v, rem));
    g_Xl[idx] = __float2bfloat16(rem);
}
__global__ void convInit(const float* __restrict__ h0, const float* __restrict__ c0,
                         const float* __restrict__ bias) {
    int idx = blockIdx.x * blockDim.x + threadIdx.x;
    if (idx >= STATE) return;
    g_ht[idx] = h0[idx];
    g_ct[idx] = c0[idx];
    if (idx < GSZ) g_biasp[idx] = bias[(idx & 3) * HSZ + (idx >> 2)];
}

// ---------------- per-step recurrent GEMM: g_part[ks][b][n-tile] = h @ Um slice ----------------
__global__ void __launch_bounds__(256, 1) step_gemm() {
    extern __shared__ char smem[];
    const uint32_t sb = smem_u32(smem);
    const int tid = threadIdx.x, wid = tid >> 5, lane = tid & 31;
    const int n0 = blockIdx.x * 128, ks = blockIdx.y;

    // A: h fp32 slice [b][ks*128 ..] -> bf16 hi/lo
    for (int i = tid; i < 4096; i += 256) {
        int b = i >> 5, kq = (i & 31) * 4;
        float4 v = *reinterpret_cast<const float4*>(&g_ht[b * HSZ + ks * 128 + kq]);
        float r0, r1, r2, r3;
        ushort4 H, L;
        H.x = bf_hi(v.x, r0); H.y = bf_hi(v.y, r1); H.z = bf_hi(v.z, r2); H.w = bf_hi(v.w, r3);
        L.x = __bfloat16_as_ushort(__float2bfloat16(r0));
        L.y = __bfloat16_as_ushort(__float2bfloat16(r1));
        L.z = __bfloat16_as_ushort(__float2bfloat16(r2));
        L.w = __bfloat16_as_ushort(__float2bfloat16(r3));
        uint32_t o = (uint32_t)b * ROWB + (uint32_t)kq * 2;
        *reinterpret_cast<ushort4*>(smem + OFF_A_HI + o) = H;
        *reinterpret_cast<ushort4*>(smem + OFF_A_LO + o) = L;
    }
    // B: Umt hi/lo slice rows n0..n0+127, k = ks*128..
    for (int i = tid; i < 4096; i += 256) {
        int hl = i >> 11, r = i & 2047, row = r >> 4, blk = r & 15;
        const __nv_bfloat16* src = (hl ? g_Umt_lo : g_Umt_hi) + (size_t)(n0 + row) * HSZ + ks * 128 + blk * 8;
        uint32_t dst = (hl ? OFF_B_LO : OFF_B_HI) + (uint32_t)row * ROWB + (uint32_t)blk * 16;
        *reinterpret_cast<uint4*>(smem + dst) = *reinterpret_cast<const uint4*>(src);
    }
    __syncthreads();

    float c[2][8][4];
#pragma unroll
    for (int i = 0; i < 2; i++)
#pragma unroll
        for (int j = 0; j < 8; j++)
#pragma unroll
            for (int q = 0; q < 4; q++) c[i][j][q] = 0.0f;

    mma_tile(sb + OFF_A_HI, sb + OFF_B_HI, lane, (wid & 3) * 32, (wid >> 2) * 64, c);
    __syncthreads();
    epilogue(smem, lane, wid, c, g_part + (size_t)ks * Bb * GSZ + n0);
}

// ---------------- input projection: g_xg[s][b][n] = X @ Wm_perm ----------------
__global__ void __launch_bounds__(256, 1) xw_gemm() {
    extern __shared__ char smem[];
    const uint32_t sb = smem_u32(smem);
    const int tid = threadIdx.x, wid = tid >> 5, lane = tid & 31;
    const int n0 = blockIdx.x * 128, s = blockIdx.y;

    float c[2][8][4];
#pragma unroll
    for (int i = 0; i < 2; i++)
#pragma unroll
        for (int j = 0; j < 8; j++)
#pragma unroll
            for (int q = 0; q < 4; q++) c[i][j][q] = 0.0f;

    for (int ck = 0; ck < 3; ck++) {
        if (ck) __syncthreads();
        for (int i = tid; i < 8192; i += 256) {
            int ab = i >> 12;
            int hl = (i >> 11) & 1, r = i & 2047, row = r >> 4, blk = r & 15;
            const __nv_bfloat16* src;
            uint32_t dst;
            if (ab == 0) {
                src = (hl ? g_Xl : g_Xh) + (size_t)(s * 128 + row) * ISZ + ck * 128 + blk * 8;
                dst = (hl ? OFF_A_LO : OFF_A_HI);
            } else {
                src = (hl ? g_Wmt_lo : g_Wmt_hi) + (size_t)(n0 + row) * ISZ + ck * 128 + blk * 8;
                dst = (hl ? OFF_B_LO : OFF_B_HI);
            }
            dst += (uint32_t)row * ROWB + (uint32_t)blk * 16;
            *reinterpret_cast<uint4*>(smem + dst) = *reinterpret_cast<const uint4*>(src);
        }
        __syncthreads();
        mma_tile(sb + OFF_A_HI, sb + OFF_B_HI, lane, (wid & 3) * 32, (wid >> 2) * 64, c);
    }
    __syncthreads();
    epilogue(smem, lane, wid, c, g_xg + (size_t)s * Bb * GSZ + n0);
}

// ---------------- fused split-K reduce + LSTM pointwise ----------------
__global__ void __launch_bounds__(256) lstm_step(float* __restrict__ out, int s) {
    int idx = blockIdx.x * 256 + threadIdx.x;   // b*768 + j
    int b = idx / HSZ, j = idx % HSZ;
    size_t g4 = (size_t)b * GSZ + j * 4;

    float4 v = *reinterpret_cast<const float4*>(&g_xg[((size_t)s * Bb) * GSZ + g4]);
    float4 bi = *reinterpret_cast<const float4*>(&g_biasp[j * 4]);
    v.x += bi.x; v.y += bi.y; v.z += bi.z; v.w += bi.w;
#pragma unroll
    for (int ks = 0; ks < 6; ks++) {
        float4 p = *reinterpret_cast<const float4*>(&g_part[(size_t)ks * Bb * GSZ + g4]);
        v.x += p.x; v.y += p.y; v.z += p.z; v.w += p.w;
    }
    float ig = fsig(v.x), fg = fsig(v.y), gg = ftanh(v.z), og = fsig(v.w);
    float cc = fg * g_ct[idx] + ig * gg;
    g_ct[idx] = cc;
    float h = og * ftanh(cc);
    g_ht[idx] = h;
    out[((size_t)b * Ss + s) * HSZ + j] = h;
    if (s == Ss - 1) {
        out[HID + idx] = h;
        out[HID + STATE + idx] = cc;
    }
}

extern "C" void kernel_launch(void* const* d_in, const int* in_sizes, int n_in,
                              void* d_out, int out_size) {
    const float* x    = (const float*)d_in[0];
    const float* h0   = (const float*)d_in[1];
    const float* c0   = (const float*)d_in[2];
    const float* W    = (const float*)d_in[3];
    const float* U    = (const float*)d_in[4];
    const float* bias = (const float*)d_in[5];
    const float* G    = (const float*)d_in[6];
    float* out = (float*)d_out;
    (void)in_sizes; (void)n_in; (void)out_size;

    cudaFuncSetAttribute(step_gemm, cudaFuncAttributeMaxDynamicSharedMemorySize, SMEMSZ);
    cudaFuncSetAttribute(xw_gemm,   cudaFuncAttributeMaxDynamicSharedMemorySize, SMEMSZ);

    convW<<<(GSZ * ISZ + 255) / 256, 256>>>(W, G);
    convU<<<(GSZ * HSZ + 255) / 256, 256>>>(U, G);
    convX<<<(Bb * Ss * ISZ + 255) / 256, 256>>>(x);
    convInit<<<(STATE + 255) / 256, 256>>>(h0, c0, bias);

    xw_gemm<<<dim3(24, 128), 256, SMEMSZ>>>();

    for (int s = 0; s < Ss; s++) {
        step_gemm<<<dim3(24, 6), 256, SMEMSZ>>>();
        lstm_step<<<STATE / 256, 256>>>(out, s);
    }
}

// round 5
// speedup vs baseline: 1.1734x; 1.0439x over previous
#include <cuda_runtime.h>
#include <cuda_bf16.h>
#include <cstdint>

#define Bb 128
#define Ss 128
#define ISZ 384
#define HSZ 768
#define GSZ 3072
#define HID (Bb*Ss*HSZ)
#define STATE (Bb*HSZ)
#define NCTA 144
#define GRIDTHREADS (NCTA*256)

// ---------------- device scratch ----------------
__device__ __nv_bfloat16 g_Umt_hi[GSZ*HSZ];
__device__ __nv_bfloat16 g_Umt_lo[GSZ*HSZ];
__device__ __nv_bfloat16 g_Wmt_hi[GSZ*ISZ];
__device__ __nv_bfloat16 g_Wmt_lo[GSZ*ISZ];
__device__ __nv_bfloat16 g_Xh[Bb*Ss*ISZ];
__device__ __nv_bfloat16 g_Xl[Bb*Ss*ISZ];
__device__ float g_xg[(size_t)Ss*Bb*GSZ];     // [s][b][n]
__device__ float g_part[6*Bb*GSZ];            // [ks][b][n]
__device__ __nv_bfloat16 g_Hh[STATE];         // h bf16 hi [b][k]
__device__ __nv_bfloat16 g_Hl[STATE];         // h bf16 lo [b][k]
__device__ float g_ct[STATE];                 // c fp32 [b][j]
__device__ float g_biasp[GSZ];
__device__ unsigned g_cnt;
__device__ volatile unsigned g_epoch;

// ---------------- helpers ----------------
__device__ __forceinline__ uint32_t smem_u32(const void* p) {
    uint32_t a;
    asm("{ .reg .u64 t; cvta.to.shared.u64 t, %1; cvt.u32.u64 %0, t; }" : "=r"(a) : "l"(p));
    return a;
}
__device__ __forceinline__ void ldsm4(uint32_t& r0, uint32_t& r1, uint32_t& r2, uint32_t& r3, uint32_t addr) {
    asm volatile("ldmatrix.sync.aligned.m8n8.x4.shared.b16 {%0,%1,%2,%3}, [%4];"
                 : "=r"(r0), "=r"(r1), "=r"(r2), "=r"(r3) : "r"(addr));
}
__device__ __forceinline__ void mma16816(float* c, uint32_t a0, uint32_t a1, uint32_t a2, uint32_t a3,
                                         uint32_t b0, uint32_t b1) {
    asm volatile("mma.sync.aligned.m16n8k16.row.col.f32.bf16.bf16.f32 "
                 "{%0,%1,%2,%3}, {%4,%5,%6,%7}, {%8,%9}, {%0,%1,%2,%3};"
                 : "+f"(c[0]), "+f"(c[1]), "+f"(c[2]), "+f"(c[3])
                 : "r"(a0), "r"(a1), "r"(a2), "r"(a3), "r"(b0), "r"(b1));
}
__device__ __forceinline__ unsigned short bf_hi(float x, float& rem) {
    __nv_bfloat16 h = __float2bfloat16(x);
    rem = x - __bfloat162float(h);
    return __bfloat16_as_ushort(h);
}
__device__ __forceinline__ float fsig(float x)  { return 1.0f / (1.0f + __expf(-x)); }
__device__ __forceinline__ float ftanh(float x) { return 2.0f / (1.0f + __expf(-2.0f * x)) - 1.0f; }

__device__ __forceinline__ void gridbar() {
    __syncthreads();
    if (threadIdx.x == 0) {
        unsigned e = g_epoch;
        __threadfence();
        if (atomicAdd(&g_cnt, 1u) == NCTA - 1u) {
            g_cnt = 0;
            __threadfence();
            g_epoch = e + 1u;
        } else {
            while (g_epoch == e) __nanosleep(64);
        }
        __threadfence();
    }
    __syncthreads();
}

// SMEM tile geometry: 128 rows x 128 bf16, row stride 272B (conflict-free ldmatrix)
#define ROWB 272
#define TILEB (128 * ROWB)
#define OFF_A_HI 0u
#define OFF_A_LO 34816u
#define OFF_B_HI 69632u
#define OFF_B_LO 104448u
#define SMEMSZ   139264

__device__ __forceinline__ void mma_tile(uint32_t sA, uint32_t sB, int lane, int mb, int nb, float c[2][8][4]) {
    uint32_t aBase = sA + (uint32_t)(mb + (lane & 15)) * ROWB + (uint32_t)(lane >> 4) * 16;
    uint32_t bBase = sB + (uint32_t)(nb + ((lane >> 4) << 3) + (lane & 7)) * ROWB + (uint32_t)((lane >> 3) & 1) * 16;
#pragma unroll
    for (int p = 0; p < 3; p++) {
        uint32_t aOff = (p == 1) ? (uint32_t)TILEB : 0u;
        uint32_t bOff = (p == 2) ? (uint32_t)TILEB : 0u;
#pragma unroll
        for (int k0 = 0; k0 < 128; k0 += 16) {
            uint32_t a[2][4];
#pragma unroll
            for (int mi = 0; mi < 2; mi++)
                ldsm4(a[mi][0], a[mi][1], a[mi][2], a[mi][3],
                      aBase + aOff + (uint32_t)(mi * 16 * ROWB + k0 * 2));
#pragma unroll
            for (int nj = 0; nj < 4; nj++) {
                uint32_t b0, b1, b2, b3;
                ldsm4(b0, b1, b2, b3, bBase + bOff + (uint32_t)(nj * 16 * ROWB + k0 * 2));
#pragma unroll
                for (int mi = 0; mi < 2; mi++) {
                    mma16816(c[mi][nj * 2],     a[mi][0], a[mi][1], a[mi][2], a[mi][3], b0, b1);
                    mma16816(c[mi][nj * 2 + 1], a[mi][0], a[mi][1], a[mi][2], a[mi][3], b2, b3);
                }
            }
        }
    }
}

__device__ __forceinline__ void epilogue(char* smem, int lane, int wid, float c[2][8][4], float* gdst) {
    float* CS = reinterpret_cast<float*>(smem);   // stride 132 floats, in A region
    const int mb = (wid & 3) * 32, nb = (wid >> 2) * 64;
    const int r0 = mb + (lane >> 2);
    const int col0 = nb + (lane & 3) * 2;
#pragma unroll
    for (int mi = 0; mi < 2; mi++)
#pragma unroll
        for (int ni = 0; ni < 8; ni++) {
            float* p0 = &CS[(r0 + mi * 16) * 132 + col0 + ni * 8];
            p0[0] = c[mi][ni][0]; p0[1] = c[mi][ni][1];
            float* p1 = &CS[(r0 + mi * 16 + 8) * 132 + col0 + ni * 8];
            p1[0] = c[mi][ni][2]; p1[1] = c[mi][ni][3];
        }
    __syncthreads();
    const int t = threadIdx.x;
    const int b = t >> 1, half = t & 1;
    const float4* src = reinterpret_cast<const float4*>(&CS[b * 132 + half * 64]);
    float4* dst = reinterpret_cast<float4*>(gdst + (size_t)b * GSZ + half * 64);
#pragma unroll
    for (int q = 0; q < 16; q++) dst[q] = src[q];
}

// ---------------- one-time conversion kernels ----------------
__global__ void convU(const float* __restrict__ U, const float* __restrict__ G) {
    int idx = blockIdx.x * blockDim.x + threadIdx.x;
    if (idx >= GSZ * HSZ) return;
    int n = idx / HSZ, k = idx % HSZ;
    int j = n >> 2, g = n & 3;
    float v = U[(size_t)k * GSZ + g * HSZ + j] * G[(k >> 5) * 24 + (j >> 5)];
    float rem;
    g_Umt_hi[idx] = __ushort_as_bfloat16(bf_hi(v, rem));
    g_Umt_lo[idx] = __float2bfloat16(rem);
}
__global__ void convW(const float* __restrict__ W, const float* __restrict__ G) {
    int idx = blockIdx.x * blockDim.x + threadIdx.x;
    if (idx >= GSZ * ISZ) return;
    int n = idx / ISZ, k = idx % ISZ;
    int j = n >> 2, g = n & 3;
    float v = W[(size_t)k * GSZ + g * HSZ + j] * G[(k >> 4) * 24 + (j >> 5)];
    float rem;
    g_Wmt_hi[idx] = __ushort_as_bfloat16(bf_hi(v, rem));
    g_Wmt_lo[idx] = __float2bfloat16(rem);
}
__global__ void convX(const float* __restrict__ x) {
    int idx = blockIdx.x * blockDim.x + threadIdx.x;
    if (idx >= Bb * Ss * ISZ) return;
    int f = idx % ISZ, r = idx / ISZ;
    int s = r >> 7, b = r & 127;
    float v = x[((size_t)b * Ss + s) * ISZ + f];
    float rem;
    g_Xh[idx] = __ushort_as_bfloat16(bf_hi(v, rem));
    g_Xl[idx] = __float2bfloat16(rem);
}
__global__ void convInit(const float* __restrict__ h0, const float* __restrict__ c0,
                         const float* __restrict__ bias) {
    int idx = blockIdx.x * blockDim.x + threadIdx.x;
    if (idx >= STATE) return;
    float rem;
    g_Hh[idx] = __ushort_as_bfloat16(bf_hi(h0[idx], rem));
    g_Hl[idx] = __float2bfloat16(rem);
    g_ct[idx] = c0[idx];
    if (idx < GSZ) g_biasp[idx] = bias[(idx & 3) * HSZ + (idx >> 2)];
}

// ---------------- input projection (unchanged from R4) ----------------
__global__ void __launch_bounds__(256, 1) xw_gemm() {
    extern __shared__ char smem[];
    const uint32_t sb = smem_u32(smem);
    const int tid = threadIdx.x, wid = tid >> 5, lane = tid & 31;
    const int n0 = blockIdx.x * 128, s = blockIdx.y;

    float c[2][8][4];
#pragma unroll
    for (int i = 0; i < 2; i++)
#pragma unroll
        for (int j = 0; j < 8; j++)
#pragma unroll
            for (int q = 0; q < 4; q++) c[i][j][q] = 0.0f;

    for (int ck = 0; ck < 3; ck++) {
        if (ck) __syncthreads();
        for (int i = tid; i < 8192; i += 256) {
            int ab = i >> 12;
            int hl = (i >> 11) & 1, r = i & 2047, row = r >> 4, blk = r & 15;
            const __nv_bfloat16* src;
            uint32_t dst;
            if (ab == 0) {
                src = (hl ? g_Xl : g_Xh) + (size_t)(s * 128 + row) * ISZ + ck * 128 + blk * 8;
                dst = (hl ? OFF_A_LO : OFF_A_HI);
            } else {
                src = (hl ? g_Wmt_lo : g_Wmt_hi) + (size_t)(n0 + row) * ISZ + ck * 128 + blk * 8;
                dst = (hl ? OFF_B_LO : OFF_B_HI);
            }
            dst += (uint32_t)row * ROWB + (uint32_t)blk * 16;
            *reinterpret_cast<uint4*>(smem + dst) = *reinterpret_cast<const uint4*>(src);
        }
        __syncthreads();
        mma_tile(sb + OFF_A_HI, sb + OFF_B_HI, lane, (wid & 3) * 32, (wid >> 2) * 64, c);
    }
    __syncthreads();
    epilogue(smem, lane, wid, c, g_xg + (size_t)s * Bb * GSZ + n0);
}

// ---------------- persistent recurrence kernel ----------------
__global__ void __launch_bounds__(256, 1) recur(float* __restrict__ out) {
    extern __shared__ char smem[];
    const uint32_t sb = smem_u32(smem);
    const int tid = threadIdx.x, wid = tid >> 5, lane = tid & 31;
    const int n0 = (blockIdx.x % 24) * 128;
    const int ks = blockIdx.x / 24;
    float* mypart = g_part + (size_t)ks * Bb * GSZ + n0;

    // Load B (Um slice) ONCE — invariant across all timesteps
    for (int i = tid; i < 4096; i += 256) {
        int hl = i >> 11, r = i & 2047, row = r >> 4, blk = r & 15;
        const __nv_bfloat16* src = (hl ? g_Umt_lo : g_Umt_hi) + (size_t)(n0 + row) * HSZ + ks * 128 + blk * 8;
        uint32_t dst = (hl ? OFF_B_LO : OFF_B_HI) + (uint32_t)row * ROWB + (uint32_t)blk * 16;
        *reinterpret_cast<uint4*>(smem + dst) = *reinterpret_cast<const uint4*>(src);
    }

    for (int s = 0; s < Ss; s++) {
        // ---- A load: h bf16 hi/lo slice [b][ks*128..] (L2-coherent loads) ----
        for (int i = tid; i < 4096; i += 256) {
            int hl = i >> 11, r = i & 2047, row = r >> 4, blk = r & 15;
            const uint4* src = reinterpret_cast<const uint4*>(
                (hl ? g_Hl : g_Hh) + (size_t)row * HSZ + ks * 128 + blk * 8);
            uint4 v = __ldcg(src);
            uint32_t dst = (hl ? OFF_A_LO : OFF_A_HI) + (uint32_t)row * ROWB + (uint32_t)blk * 16;
            *reinterpret_cast<uint4*>(smem + dst) = v;
        }
        __syncthreads();

        float c[2][8][4];
#pragma unroll
        for (int i = 0; i < 2; i++)
#pragma unroll
            for (int j = 0; j < 8; j++)
#pragma unroll
                for (int q = 0; q < 4; q++) c[i][j][q] = 0.0f;

        mma_tile(sb + OFF_A_HI, sb + OFF_B_HI, lane, (wid & 3) * 32, (wid >> 2) * 64, c);
        __syncthreads();
        epilogue(smem, lane, wid, c, mypart);     // partials -> global (L2)
        __threadfence();
        gridbar();

        // ---- LSTM phase: distributed over whole grid ----
        for (int idx = blockIdx.x * 256 + tid; idx < STATE; idx += GRIDTHREADS) {
            int b = idx / HSZ, j = idx % HSZ;
            size_t g4 = (size_t)b * GSZ + j * 4;
            float4 v = *reinterpret_cast<const float4*>(&g_xg[((size_t)s * Bb) * GSZ + g4]);
            float4 bi = *reinterpret_cast<const float4*>(&g_biasp[j * 4]);
            v.x += bi.x; v.y += bi.y; v.z += bi.z; v.w += bi.w;
#pragma unroll
            for (int kk = 0; kk < 6; kk++) {
                float4 p = __ldcg(reinterpret_cast<const float4*>(&g_part[(size_t)kk * Bb * GSZ + g4]));
                v.x += p.x; v.y += p.y; v.z += p.z; v.w += p.w;
            }
            float ig = fsig(v.x), fg = fsig(v.y), gg = ftanh(v.z), og = fsig(v.w);
            float cc = fg * g_ct[idx] + ig * gg;
            g_ct[idx] = cc;
            float h = og * ftanh(cc);
            float rem;
            g_Hh[idx] = __ushort_as_bfloat16(bf_hi(h, rem));
            g_Hl[idx] = __float2bfloat16(rem);
            out[((size_t)b * Ss + s) * HSZ + j] = h;
            if (s == Ss - 1) {
                out[HID + idx] = h;
                out[HID + STATE + idx] = cc;
            }
        }
        __threadfence();
        gridbar();
    }
}

extern "C" void kernel_launch(void* const* d_in, const int* in_sizes, int n_in,
                              void* d_out, int out_size) {
    const float* x    = (const float*)d_in[0];
    const float* h0   = (const float*)d_in[1];
    const float* c0   = (const float*)d_in[2];
    const float* W    = (const float*)d_in[3];
    const float* U    = (const float*)d_in[4];
    const float* bias = (const float*)d_in[5];
    const float* G    = (const float*)d_in[6];
    float* out = (float*)d_out;
    (void)in_sizes; (void)n_in; (void)out_size;

    cudaFuncSetAttribute(xw_gemm, cudaFuncAttributeMaxDynamicSharedMemorySize, SMEMSZ);
    cudaFuncSetAttribute(recur,   cudaFuncAttributeMaxDynamicSharedMemorySize, SMEMSZ);

    convW<<<(GSZ * ISZ + 255) / 256, 256>>>(W, G);
    convU<<<(GSZ * HSZ + 255) / 256, 256>>>(U, G);
    convX<<<(Bb * Ss * ISZ + 255) / 256, 256>>>(x);
    convInit<<<(STATE + 255) / 256, 256>>>(h0, c0, bias);

    xw_gemm<<<dim3(24, 128), 256, SMEMSZ>>>();
    recur<<<NCTA, 256, SMEMSZ>>>(out);
}